// round 4
// baseline (speedup 1.0000x reference)
#include <cuda_runtime.h>
#include <cuda_bf16.h>
#include <math.h>

// ---------------- problem constants ----------------
#define MAXN 50000
#define MAXE 800000
#define MAXF 256

// ---------------- device scratch (no allocations allowed) ----------------
__device__ float d_deg[MAXN];
__device__ float d_dinv[MAXN];
__device__ float d_bufA[(size_t)MAXN * MAXF];
__device__ float d_bufB[(size_t)MAXN * MAXF];

// ---------------- degree / dinv ----------------
__global__ void deg_init_kernel(float* __restrict__ deg, int n) {
    int i = blockIdx.x * blockDim.x + threadIdx.x;
    if (i < n) deg[i] = 1.0f;  // self loop
}

__global__ void deg_count_kernel(const int* __restrict__ dst, float* __restrict__ deg, int e) {
    int i = blockIdx.x * blockDim.x + threadIdx.x;
    if (i < e) atomicAdd(&deg[dst[i]], 1.0f);
}

__global__ void dinv_kernel(const float* __restrict__ deg, float* __restrict__ dinv, int n) {
    int i = blockIdx.x * blockDim.x + threadIdx.x;
    if (i < n) dinv[i] = rsqrtf(deg[i]);
}

// ---------------- self-loop + bias init of the aggregation buffer ----------------
__global__ void self_bias_kernel(const float* __restrict__ h, const float* __restrict__ dinv,
                                 const float* __restrict__ b, float* __restrict__ agg,
                                 int n, int F) {
    int idx = blockIdx.x * blockDim.x + threadIdx.x;
    int total = n * F;
    if (idx >= total) return;
    int i = idx / F;
    int f = idx - i * F;
    float di = dinv[i];
    agg[idx] = h[idx] * (di * di) + b[f];
}

// ---------------- edge scatter (atomic) ----------------
__global__ void scatter_kernel(const int* __restrict__ src, const int* __restrict__ dst,
                               const float* __restrict__ dinv, const float* __restrict__ h,
                               float* __restrict__ agg, int e, int F) {
    int chunks = F >> 2;  // float4 chunks per edge
    long long idx = (long long)blockIdx.x * blockDim.x + threadIdx.x;
    long long total = (long long)e * chunks;
    if (idx >= total) return;
    int ed = (int)(idx / chunks);
    int f = (int)(idx - (long long)ed * chunks) << 2;
    int s = src[ed], d = dst[ed];
    float coef = dinv[s] * dinv[d];
    const float4 v = *reinterpret_cast<const float4*>(h + (size_t)s * F + f);
    float* out = agg + (size_t)d * F + f;
    atomicAdd(out + 0, v.x * coef);
    atomicAdd(out + 1, v.y * coef);
    atomicAdd(out + 2, v.z * coef);
    atomicAdd(out + 3, v.w * coef);
}

// ---------------- layernorm + elu (in place), one block per node ----------------
template <int F>
__global__ void ln_elu_kernel(float* __restrict__ x, const float* __restrict__ g,
                              const float* __restrict__ be) {
    constexpr int NW = F / 32;
    __shared__ float warpsum[NW];
    __shared__ float bcast;
    int node = blockIdx.x;
    float* row = x + (size_t)node * F;
    int t = threadIdx.x;
    float v = row[t];

    // mean
    float s = v;
    #pragma unroll
    for (int o = 16; o; o >>= 1) s += __shfl_xor_sync(0xffffffffu, s, o);
    int lane = t & 31, w = t >> 5;
    if (lane == 0) warpsum[w] = s;
    __syncthreads();
    if (t == 0) {
        float tot = 0.f;
        #pragma unroll
        for (int i = 0; i < NW; i++) tot += warpsum[i];
        bcast = tot / (float)F;
    }
    __syncthreads();
    float mu = bcast;

    // variance
    float d = v - mu;
    s = d * d;
    #pragma unroll
    for (int o = 16; o; o >>= 1) s += __shfl_xor_sync(0xffffffffu, s, o);
    __syncthreads();  // protect warpsum reuse
    if (lane == 0) warpsum[w] = s;
    __syncthreads();
    if (t == 0) {
        float tot = 0.f;
        #pragma unroll
        for (int i = 0; i < NW; i++) tot += warpsum[i];
        bcast = rsqrtf(tot / (float)F + 1e-5f);
    }
    __syncthreads();
    float rstd = bcast;

    float y = d * rstd * g[t] + be[t];
    row[t] = (y > 0.f) ? y : expm1f(y);
}

// ---------------- tiled fp32 GEMM: C[M,Nc] = A[M,K] @ W[K,Nc] (+bias) ----------------
// BM=BN=64, BK=16, 256 threads, each thread computes 4x4.
template <bool BIAS>
__global__ void gemm_kernel(const float* __restrict__ A, const float* __restrict__ W,
                            const float* __restrict__ bias, float* __restrict__ C,
                            int M, int K, int Nc) {
    __shared__ float As[16][68];  // padded, rows 16B-aligned (68*4=272 bytes)
    __shared__ float Ws[16][68];
    int tid = threadIdx.x;
    int tx = tid & 15;       // 0..15  (N direction)
    int ty = tid >> 4;       // 0..15  (M direction)
    int blockM = blockIdx.y * 64;
    int blockN = blockIdx.x * 64;

    int aRow = tid >> 2;            // 0..63
    int aCol = (tid & 3) << 2;      // 0,4,8,12
    int wRow = tid >> 4;            // 0..15
    int wCol = (tid & 15) << 2;     // 0..60

    float acc[4][4];
    #pragma unroll
    for (int i = 0; i < 4; i++)
        #pragma unroll
        for (int j = 0; j < 4; j++) acc[i][j] = 0.f;

    for (int k0 = 0; k0 < K; k0 += 16) {
        // A tile (transposed into As[k][m])
        float4 av = make_float4(0.f, 0.f, 0.f, 0.f);
        int gr = blockM + aRow;
        if (gr < M) av = *reinterpret_cast<const float4*>(A + (size_t)gr * K + k0 + aCol);
        As[aCol + 0][aRow] = av.x;
        As[aCol + 1][aRow] = av.y;
        As[aCol + 2][aRow] = av.z;
        As[aCol + 3][aRow] = av.w;
        // W tile
        float4 wv = make_float4(0.f, 0.f, 0.f, 0.f);
        int gc = blockN + wCol;
        if (gc < Nc) wv = *reinterpret_cast<const float4*>(W + (size_t)(k0 + wRow) * Nc + gc);
        *reinterpret_cast<float4*>(&Ws[wRow][wCol]) = wv;
        __syncthreads();

        #pragma unroll
        for (int kk = 0; kk < 16; kk++) {
            float4 a4 = *reinterpret_cast<const float4*>(&As[kk][ty << 2]);
            float4 b4 = *reinterpret_cast<const float4*>(&Ws[kk][tx << 2]);
            float a[4] = {a4.x, a4.y, a4.z, a4.w};
            float b[4] = {b4.x, b4.y, b4.z, b4.w};
            #pragma unroll
            for (int i = 0; i < 4; i++)
                #pragma unroll
                for (int j = 0; j < 4; j++) acc[i][j] += a[i] * b[j];
        }
        __syncthreads();
    }

    #pragma unroll
    for (int i = 0; i < 4; i++) {
        int r = blockM + (ty << 2) + i;
        if (r >= M) continue;
        #pragma unroll
        for (int j = 0; j < 4; j++) {
            int c = blockN + (tx << 2) + j;
            if (c < Nc) {
                float v = acc[i][j];
                if (BIAS) v += bias[c];
                C[(size_t)r * Nc + c] = v;
            }
        }
    }
}

// ---------------- launch helpers ----------------
static inline void launch_gemm(const float* A, const float* W, const float* bias, float* C,
                               int M, int K, int Nc) {
    dim3 grid((Nc + 63) / 64, (M + 63) / 64);
    if (bias)
        gemm_kernel<true><<<grid, 256>>>(A, W, bias, C, M, K, Nc);
    else
        gemm_kernel<false><<<grid, 256>>>(A, W, nullptr, C, M, K, Nc);
}

extern "C" void kernel_launch(void* const* d_in, const int* in_sizes, int n_in,
                              void* d_out, int out_size) {
    const float* x   = (const float*)d_in[0];
    const int*   ei  = (const int*)d_in[1];
    const float* W1  = (const float*)d_in[2];
    const float* b1  = (const float*)d_in[3];
    const float* g1  = (const float*)d_in[4];
    const float* be1 = (const float*)d_in[5];
    const float* W2  = (const float*)d_in[6];
    const float* b2  = (const float*)d_in[7];
    const float* g2  = (const float*)d_in[8];
    const float* be2 = (const float*)d_in[9];
    const float* W3  = (const float*)d_in[10];
    const float* b3  = (const float*)d_in[11];
    const float* g3  = (const float*)d_in[12];
    const float* be3 = (const float*)d_in[13];
    const float* Wl1 = (const float*)d_in[14];
    const float* bl1 = (const float*)d_in[15];
    const float* g4  = (const float*)d_in[16];
    const float* be4 = (const float*)d_in[17];
    const float* Wl2 = (const float*)d_in[18];
    const float* bl2 = (const float*)d_in[19];
    float* out = (float*)d_out;

    const int N = in_sizes[0] / 128;
    const int E = in_sizes[1] / 2;
    const int* src = ei;
    const int* dst = ei + E;

    float *deg, *dinv, *bufA, *bufB;
    cudaGetSymbolAddress((void**)&deg,  d_deg);
    cudaGetSymbolAddress((void**)&dinv, d_dinv);
    cudaGetSymbolAddress((void**)&bufA, d_bufA);
    cudaGetSymbolAddress((void**)&bufB, d_bufB);

    // degree + dinv
    deg_init_kernel<<<(N + 255) / 256, 256>>>(deg, N);
    deg_count_kernel<<<(E + 255) / 256, 256>>>(dst, deg, E);
    dinv_kernel<<<(N + 255) / 256, 256>>>(deg, dinv, N);

    // ---- layer 1: gcn_conv(x, W1) -> LN -> ELU   (F = 128)
    launch_gemm(x, W1, nullptr, bufA, N, 128, 128);
    {
        int total = N * 128;
        self_bias_kernel<<<(total + 255) / 256, 256>>>(bufA, dinv, b1, bufB, N, 128);
        long long work = (long long)E * (128 / 4);
        scatter_kernel<<<(int)((work + 255) / 256), 256>>>(src, dst, dinv, bufA, bufB, E, 128);
        ln_elu_kernel<128><<<N, 128>>>(bufB, g1, be1);
    }

    // ---- layer 2: gcn_conv(h, W2) -> LN -> ELU   (F = 256)
    launch_gemm(bufB, W2, nullptr, bufA, N, 128, 256);
    {
        int total = N * 256;
        self_bias_kernel<<<(total + 255) / 256, 256>>>(bufA, dinv, b2, bufB, N, 256);
        long long work = (long long)E * (256 / 4);
        scatter_kernel<<<(int)((work + 255) / 256), 256>>>(src, dst, dinv, bufA, bufB, E, 256);
        ln_elu_kernel<256><<<N, 256>>>(bufB, g2, be2);
    }

    // ---- layer 3: gcn_conv(h, W3) -> LN -> ELU   (F = 128)
    launch_gemm(bufB, W3, nullptr, bufA, N, 256, 128);
    {
        int total = N * 128;
        self_bias_kernel<<<(total + 255) / 256, 256>>>(bufA, dinv, b3, bufB, N, 128);
        long long work = (long long)E * (128 / 4);
        scatter_kernel<<<(int)((work + 255) / 256), 256>>>(src, dst, dinv, bufA, bufB, E, 128);
        ln_elu_kernel<128><<<N, 128>>>(bufB, g3, be3);
    }

    // ---- head: linear -> LN -> ELU -> linear
    launch_gemm(bufB, Wl1, bl1, bufA, N, 128, 64);
    ln_elu_kernel<64><<<N, 64>>>(bufA, g4, be4);
    launch_gemm(bufA, Wl2, bl2, out, N, 64, 500);
}

// round 5
// speedup vs baseline: 1.9641x; 1.9641x over previous
#include <cuda_runtime.h>
#include <cuda_bf16.h>
#include <math.h>

// ---------------- problem constants ----------------
#define MAXN 50000
#define MAXE 800000
#define MAXF 256

// ---------------- device scratch (no allocations allowed) ----------------
__device__ float d_dinv[MAXN];
__device__ int   d_cnt[MAXN];
__device__ int   d_rowptr[MAXN + 1];
__device__ int   d_cursor[MAXN];
__device__ int   d_csr_src[MAXE];
__device__ float d_csr_coef[MAXE];
__device__ float d_bufA[(size_t)MAXN * MAXF];
__device__ float d_bufB[(size_t)MAXN * MAXF];

// ---------------- CSR construction ----------------
__global__ void zero_cnt_kernel(int* __restrict__ cnt, int n) {
    int i = blockIdx.x * blockDim.x + threadIdx.x;
    if (i < n) cnt[i] = 0;
}

__global__ void count_kernel(const int* __restrict__ dst, int* __restrict__ cnt, int e) {
    int i = blockIdx.x * blockDim.x + threadIdx.x;
    if (i < e) atomicAdd(&cnt[dst[i]], 1);
}

__global__ void dinv_kernel(const int* __restrict__ cnt, float* __restrict__ dinv, int n) {
    int i = blockIdx.x * blockDim.x + threadIdx.x;
    if (i < n) dinv[i] = rsqrtf((float)cnt[i] + 1.0f);  // +1 self loop
}

// single-block exclusive scan over n counters -> rowptr[0..n]
__global__ void scan_kernel(const int* __restrict__ cnt, int* __restrict__ rowptr, int n) {
    __shared__ int wsum[32];
    __shared__ int carry_s;
    if (threadIdx.x == 0) carry_s = 0;
    __syncthreads();
    int lane = threadIdx.x & 31, w = threadIdx.x >> 5;
    for (int base = 0; base < n; base += blockDim.x) {
        int i = base + threadIdx.x;
        int v = (i < n) ? cnt[i] : 0;
        int x = v;
        #pragma unroll
        for (int o = 1; o < 32; o <<= 1) {
            int y = __shfl_up_sync(0xffffffffu, x, o);
            if (lane >= o) x += y;
        }
        if (lane == 31) wsum[w] = x;
        __syncthreads();
        if (w == 0) {
            int s = wsum[lane];
            #pragma unroll
            for (int o = 1; o < 32; o <<= 1) {
                int y = __shfl_up_sync(0xffffffffu, s, o);
                if (lane >= o) s += y;
            }
            wsum[lane] = s;
        }
        __syncthreads();
        int incl = x + (w ? wsum[w - 1] : 0) + carry_s;
        if (i < n) rowptr[i] = incl - v;
        if (i == n - 1) rowptr[n] = incl;
        __syncthreads();
        if (threadIdx.x == blockDim.x - 1) carry_s = incl;
        __syncthreads();
    }
}

__global__ void cursor_init_kernel(const int* __restrict__ rowptr, int* __restrict__ cursor, int n) {
    int i = blockIdx.x * blockDim.x + threadIdx.x;
    if (i < n) cursor[i] = rowptr[i];
}

__global__ void fill_kernel(const int* __restrict__ src, const int* __restrict__ dst,
                            const float* __restrict__ dinv, int* __restrict__ cursor,
                            int* __restrict__ csr_src, float* __restrict__ csr_coef, int e) {
    int i = blockIdx.x * blockDim.x + threadIdx.x;
    if (i >= e) return;
    int s = src[i], d = dst[i];
    int pos = atomicAdd(&cursor[d], 1);
    csr_src[pos] = s;
    csr_coef[pos] = dinv[s] * dinv[d];
}

// ---------------- fused gather + self-loop + bias + LayerNorm + ELU ----------------
// one block per node, F threads; each thread owns one feature.
template <int F>
__global__ void gather_ln_kernel(const float* __restrict__ h,
                                 const int* __restrict__ rowptr,
                                 const int* __restrict__ csr_src,
                                 const float* __restrict__ csr_coef,
                                 const float* __restrict__ dinv,
                                 const float* __restrict__ bias,
                                 const float* __restrict__ g,
                                 const float* __restrict__ be,
                                 float* __restrict__ out) {
    constexpr int NW = F / 32;
    __shared__ float warpsum[NW];
    __shared__ float bcast;
    int node = blockIdx.x;
    int t = threadIdx.x;
    float di = dinv[node];
    float acc = h[(size_t)node * F + t] * (di * di) + bias[t];

    int e = rowptr[node];
    int end = rowptr[node + 1];
    // unroll by 2 to get 2 independent loads in flight
    for (; e + 1 < end; e += 2) {
        int s0 = __ldg(&csr_src[e]);
        int s1 = __ldg(&csr_src[e + 1]);
        float c0 = __ldg(&csr_coef[e]);
        float c1 = __ldg(&csr_coef[e + 1]);
        float v0 = h[(size_t)s0 * F + t];
        float v1 = h[(size_t)s1 * F + t];
        acc += v0 * c0;
        acc += v1 * c1;
    }
    if (e < end) {
        int s0 = __ldg(&csr_src[e]);
        float c0 = __ldg(&csr_coef[e]);
        acc += h[(size_t)s0 * F + t] * c0;
    }

    // LayerNorm + ELU over the row held by this block
    float s = acc;
    #pragma unroll
    for (int o = 16; o; o >>= 1) s += __shfl_xor_sync(0xffffffffu, s, o);
    int lane = t & 31, w = t >> 5;
    if (lane == 0) warpsum[w] = s;
    __syncthreads();
    if (t == 0) {
        float tot = 0.f;
        #pragma unroll
        for (int i = 0; i < NW; i++) tot += warpsum[i];
        bcast = tot / (float)F;
    }
    __syncthreads();
    float mu = bcast;

    float d = acc - mu;
    s = d * d;
    #pragma unroll
    for (int o = 16; o; o >>= 1) s += __shfl_xor_sync(0xffffffffu, s, o);
    __syncthreads();
    if (lane == 0) warpsum[w] = s;
    __syncthreads();
    if (t == 0) {
        float tot = 0.f;
        #pragma unroll
        for (int i = 0; i < NW; i++) tot += warpsum[i];
        bcast = rsqrtf(tot / (float)F + 1e-5f);
    }
    __syncthreads();
    float rstd = bcast;

    float y = d * rstd * g[t] + be[t];
    out[(size_t)node * F + t] = (y > 0.f) ? y : expm1f(y);
}

// ---------------- plain layernorm + elu (head, F=64) ----------------
template <int F>
__global__ void ln_elu_kernel(float* __restrict__ x, const float* __restrict__ g,
                              const float* __restrict__ be) {
    constexpr int NW = F / 32;
    __shared__ float warpsum[NW];
    __shared__ float bcast;
    int node = blockIdx.x;
    float* row = x + (size_t)node * F;
    int t = threadIdx.x;
    float v = row[t];

    float s = v;
    #pragma unroll
    for (int o = 16; o; o >>= 1) s += __shfl_xor_sync(0xffffffffu, s, o);
    int lane = t & 31, w = t >> 5;
    if (lane == 0) warpsum[w] = s;
    __syncthreads();
    if (t == 0) {
        float tot = 0.f;
        #pragma unroll
        for (int i = 0; i < NW; i++) tot += warpsum[i];
        bcast = tot / (float)F;
    }
    __syncthreads();
    float mu = bcast;

    float d = v - mu;
    s = d * d;
    #pragma unroll
    for (int o = 16; o; o >>= 1) s += __shfl_xor_sync(0xffffffffu, s, o);
    __syncthreads();
    if (lane == 0) warpsum[w] = s;
    __syncthreads();
    if (t == 0) {
        float tot = 0.f;
        #pragma unroll
        for (int i = 0; i < NW; i++) tot += warpsum[i];
        bcast = rsqrtf(tot / (float)F + 1e-5f);
    }
    __syncthreads();
    float rstd = bcast;

    float y = d * rstd * g[t] + be[t];
    row[t] = (y > 0.f) ? y : expm1f(y);
}

// ---------------- tiled fp32 GEMM: C[M,Nc] = A[M,K] @ W[K,Nc] (+bias) ----------------
template <bool BIAS>
__global__ void gemm_kernel(const float* __restrict__ A, const float* __restrict__ W,
                            const float* __restrict__ bias, float* __restrict__ C,
                            int M, int K, int Nc) {
    __shared__ float As[16][68];
    __shared__ float Ws[16][68];
    int tid = threadIdx.x;
    int tx = tid & 15;
    int ty = tid >> 4;
    int blockM = blockIdx.y * 64;
    int blockN = blockIdx.x * 64;

    int aRow = tid >> 2;
    int aCol = (tid & 3) << 2;
    int wRow = tid >> 4;
    int wCol = (tid & 15) << 2;

    float acc[4][4];
    #pragma unroll
    for (int i = 0; i < 4; i++)
        #pragma unroll
        for (int j = 0; j < 4; j++) acc[i][j] = 0.f;

    for (int k0 = 0; k0 < K; k0 += 16) {
        float4 av = make_float4(0.f, 0.f, 0.f, 0.f);
        int gr = blockM + aRow;
        if (gr < M) av = *reinterpret_cast<const float4*>(A + (size_t)gr * K + k0 + aCol);
        As[aCol + 0][aRow] = av.x;
        As[aCol + 1][aRow] = av.y;
        As[aCol + 2][aRow] = av.z;
        As[aCol + 3][aRow] = av.w;
        float4 wv = make_float4(0.f, 0.f, 0.f, 0.f);
        int gc = blockN + wCol;
        if (gc < Nc) wv = *reinterpret_cast<const float4*>(W + (size_t)(k0 + wRow) * Nc + gc);
        *reinterpret_cast<float4*>(&Ws[wRow][wCol]) = wv;
        __syncthreads();

        #pragma unroll
        for (int kk = 0; kk < 16; kk++) {
            float4 a4 = *reinterpret_cast<const float4*>(&As[kk][ty << 2]);
            float4 b4 = *reinterpret_cast<const float4*>(&Ws[kk][tx << 2]);
            float a[4] = {a4.x, a4.y, a4.z, a4.w};
            float b[4] = {b4.x, b4.y, b4.z, b4.w};
            #pragma unroll
            for (int i = 0; i < 4; i++)
                #pragma unroll
                for (int j = 0; j < 4; j++) acc[i][j] += a[i] * b[j];
        }
        __syncthreads();
    }

    #pragma unroll
    for (int i = 0; i < 4; i++) {
        int r = blockM + (ty << 2) + i;
        if (r >= M) continue;
        #pragma unroll
        for (int j = 0; j < 4; j++) {
            int c = blockN + (tx << 2) + j;
            if (c < Nc) {
                float v = acc[i][j];
                if (BIAS) v += bias[c];
                C[(size_t)r * Nc + c] = v;
            }
        }
    }
}

static inline void launch_gemm(const float* A, const float* W, const float* bias, float* C,
                               int M, int K, int Nc) {
    dim3 grid((Nc + 63) / 64, (M + 63) / 64);
    if (bias)
        gemm_kernel<true><<<grid, 256>>>(A, W, bias, C, M, K, Nc);
    else
        gemm_kernel<false><<<grid, 256>>>(A, W, nullptr, C, M, K, Nc);
}

extern "C" void kernel_launch(void* const* d_in, const int* in_sizes, int n_in,
                              void* d_out, int out_size) {
    const float* x   = (const float*)d_in[0];
    const int*   ei  = (const int*)d_in[1];
    const float* W1  = (const float*)d_in[2];
    const float* b1  = (const float*)d_in[3];
    const float* g1  = (const float*)d_in[4];
    const float* be1 = (const float*)d_in[5];
    const float* W2  = (const float*)d_in[6];
    const float* b2  = (const float*)d_in[7];
    const float* g2  = (const float*)d_in[8];
    const float* be2 = (const float*)d_in[9];
    const float* W3  = (const float*)d_in[10];
    const float* b3  = (const float*)d_in[11];
    const float* g3  = (const float*)d_in[12];
    const float* be3 = (const float*)d_in[13];
    const float* Wl1 = (const float*)d_in[14];
    const float* bl1 = (const float*)d_in[15];
    const float* g4  = (const float*)d_in[16];
    const float* be4 = (const float*)d_in[17];
    const float* Wl2 = (const float*)d_in[18];
    const float* bl2 = (const float*)d_in[19];
    float* out = (float*)d_out;

    const int N = in_sizes[0] / 128;
    const int E = in_sizes[1] / 2;
    const int* src = ei;
    const int* dst = ei + E;

    float *dinv, *bufA, *bufB, *csr_coef;
    int *cnt, *rowptr, *cursor, *csr_src;
    cudaGetSymbolAddress((void**)&dinv,     d_dinv);
    cudaGetSymbolAddress((void**)&cnt,      d_cnt);
    cudaGetSymbolAddress((void**)&rowptr,   d_rowptr);
    cudaGetSymbolAddress((void**)&cursor,   d_cursor);
    cudaGetSymbolAddress((void**)&csr_src,  d_csr_src);
    cudaGetSymbolAddress((void**)&csr_coef, d_csr_coef);
    cudaGetSymbolAddress((void**)&bufA,     d_bufA);
    cudaGetSymbolAddress((void**)&bufB,     d_bufB);

    // ---- CSR build ----
    zero_cnt_kernel<<<(N + 255) / 256, 256>>>(cnt, N);
    count_kernel<<<(E + 255) / 256, 256>>>(dst, cnt, E);
    dinv_kernel<<<(N + 255) / 256, 256>>>(cnt, dinv, N);
    scan_kernel<<<1, 1024>>>(cnt, rowptr, N);
    cursor_init_kernel<<<(N + 255) / 256, 256>>>(rowptr, cursor, N);
    fill_kernel<<<(E + 255) / 256, 256>>>(src, dst, dinv, cursor, csr_src, csr_coef, E);

    // ---- layer 1: gemm -> fused gather+LN+ELU (F = 128)
    launch_gemm(x, W1, nullptr, bufA, N, 128, 128);
    gather_ln_kernel<128><<<N, 128>>>(bufA, rowptr, csr_src, csr_coef, dinv, b1, g1, be1, bufB);

    // ---- layer 2 (F = 256)
    launch_gemm(bufB, W2, nullptr, bufA, N, 128, 256);
    gather_ln_kernel<256><<<N, 256>>>(bufA, rowptr, csr_src, csr_coef, dinv, b2, g2, be2, bufB);

    // ---- layer 3 (F = 128)
    launch_gemm(bufB, W3, nullptr, bufA, N, 256, 128);
    gather_ln_kernel<128><<<N, 128>>>(bufA, rowptr, csr_src, csr_coef, dinv, b3, g3, be3, bufB);

    // ---- head: linear -> LN -> ELU -> linear
    launch_gemm(bufB, Wl1, bl1, bufA, N, 128, 64);
    ln_elu_kernel<64><<<N, 64>>>(bufA, g4, be4);
    launch_gemm(bufA, Wl2, bl2, out, N, 64, 500);
}

// round 6
// speedup vs baseline: 2.6245x; 1.3363x over previous
#include <cuda_runtime.h>
#include <cuda_bf16.h>
#include <math.h>
#include <stdint.h>

// ---------------- problem constants ----------------
#define MAXN 50000
#define MAXE 800000
#define MAXF 256
#define SCAN_BLK 256
#define MAX_PARTIALS 256   // supports N up to 65536

// ---------------- device scratch (no allocations allowed) ----------------
__device__ float d_dinv[MAXN];
__device__ int   d_cnt[MAXN];
__device__ int   d_rowptr[MAXN + 1];
__device__ int   d_cursor[MAXN];
__device__ int   d_partial[MAX_PARTIALS];
__device__ int   d_csr_src[MAXE];
__device__ float d_csr_coef[MAXE];
__device__ float d_bufA[(size_t)MAXN * MAXF];
__device__ float d_bufB[(size_t)MAXN * MAXF];

// ---------------- CSR construction ----------------
__global__ void zero_cnt_kernel(int* __restrict__ cnt, int n) {
    int i = blockIdx.x * blockDim.x + threadIdx.x;
    if (i < n) cnt[i] = 0;
}

__global__ void count_kernel(const int* __restrict__ dst, int* __restrict__ cnt, int e) {
    int i = blockIdx.x * blockDim.x + threadIdx.x;
    if (i < e) atomicAdd(&cnt[dst[i]], 1);
}

__global__ void dinv_kernel(const int* __restrict__ cnt, float* __restrict__ dinv, int n) {
    int i = blockIdx.x * blockDim.x + threadIdx.x;
    if (i < n) dinv[i] = rsqrtf((float)cnt[i] + 1.0f);  // +1 self loop
}

// phase 1: per-block sums of cnt (256 elems per block)
__global__ void block_reduce_kernel(const int* __restrict__ cnt, int* __restrict__ partial, int n) {
    __shared__ int ws[8];
    int i = blockIdx.x * SCAN_BLK + threadIdx.x;
    int v = (i < n) ? cnt[i] : 0;
    #pragma unroll
    for (int o = 16; o; o >>= 1) v += __shfl_xor_sync(0xffffffffu, v, o);
    int lane = threadIdx.x & 31, w = threadIdx.x >> 5;
    if (lane == 0) ws[w] = v;
    __syncthreads();
    if (threadIdx.x == 0) {
        int s = 0;
        #pragma unroll
        for (int k = 0; k < 8; k++) s += ws[k];
        partial[blockIdx.x] = s;
    }
}

// phase 2: single block exclusive scan of up to 256 partials (in place)
__global__ void scan_partials_kernel(int* __restrict__ partial, int nb) {
    __shared__ int ws[8];
    int t = threadIdx.x;
    int v = (t < nb) ? partial[t] : 0;
    int lane = t & 31, w = t >> 5;
    int x = v;
    #pragma unroll
    for (int o = 1; o < 32; o <<= 1) {
        int y = __shfl_up_sync(0xffffffffu, x, o);
        if (lane >= o) x += y;
    }
    if (lane == 31) ws[w] = x;
    __syncthreads();
    if (w == 0 && lane < 8) {
        int s = ws[lane];
        #pragma unroll
        for (int o = 1; o < 8; o <<= 1) {
            int y = __shfl_up_sync(0xffu, s, o);
            if (lane >= o) s += y;
        }
        ws[lane] = s;
    }
    __syncthreads();
    int incl = x + (w ? ws[w - 1] : 0);
    if (t < nb) partial[t] = incl - v;   // exclusive
}

// phase 3: per-block exclusive scan + block offset -> rowptr, also init cursor
__global__ void scan_final_kernel(const int* __restrict__ cnt, const int* __restrict__ partial,
                                  int* __restrict__ rowptr, int* __restrict__ cursor, int n) {
    __shared__ int ws[8];
    int i = blockIdx.x * SCAN_BLK + threadIdx.x;
    int t = threadIdx.x;
    int v = (i < n) ? cnt[i] : 0;
    int lane = t & 31, w = t >> 5;
    int x = v;
    #pragma unroll
    for (int o = 1; o < 32; o <<= 1) {
        int y = __shfl_up_sync(0xffffffffu, x, o);
        if (lane >= o) x += y;
    }
    if (lane == 31) ws[w] = x;
    __syncthreads();
    if (w == 0 && lane < 8) {
        int s = ws[lane];
        #pragma unroll
        for (int o = 1; o < 8; o <<= 1) {
            int y = __shfl_up_sync(0xffu, s, o);
            if (lane >= o) s += y;
        }
        ws[lane] = s;
    }
    __syncthreads();
    int incl = x + (w ? ws[w - 1] : 0) + partial[blockIdx.x];
    if (i < n) {
        int excl = incl - v;
        rowptr[i] = excl;
        cursor[i] = excl;
        if (i == n - 1) rowptr[n] = incl;
    }
}

__global__ void fill_kernel(const int* __restrict__ src, const int* __restrict__ dst,
                            const float* __restrict__ dinv, int* __restrict__ cursor,
                            int* __restrict__ csr_src, float* __restrict__ csr_coef, int e) {
    int i = blockIdx.x * blockDim.x + threadIdx.x;
    if (i >= e) return;
    int s = src[i], d = dst[i];
    int pos = atomicAdd(&cursor[d], 1);
    csr_src[pos] = s;
    csr_coef[pos] = dinv[s] * dinv[d];
}

// ---------------- fused gather + self-loop + bias + LayerNorm + ELU ----------------
template <int F>
__global__ void gather_ln_kernel(const float* __restrict__ h,
                                 const int* __restrict__ rowptr,
                                 const int* __restrict__ csr_src,
                                 const float* __restrict__ csr_coef,
                                 const float* __restrict__ dinv,
                                 const float* __restrict__ bias,
                                 const float* __restrict__ g,
                                 const float* __restrict__ be,
                                 float* __restrict__ out) {
    constexpr int NW = F / 32;
    __shared__ float warpsum[NW];
    __shared__ float bcast;
    int node = blockIdx.x;
    int t = threadIdx.x;
    float di = dinv[node];
    float acc = h[(size_t)node * F + t] * (di * di) + bias[t];

    int e = rowptr[node];
    int end = rowptr[node + 1];
    for (; e + 1 < end; e += 2) {
        int s0 = __ldg(&csr_src[e]);
        int s1 = __ldg(&csr_src[e + 1]);
        float c0 = __ldg(&csr_coef[e]);
        float c1 = __ldg(&csr_coef[e + 1]);
        float v0 = h[(size_t)s0 * F + t];
        float v1 = h[(size_t)s1 * F + t];
        acc += v0 * c0;
        acc += v1 * c1;
    }
    if (e < end) {
        int s0 = __ldg(&csr_src[e]);
        float c0 = __ldg(&csr_coef[e]);
        acc += h[(size_t)s0 * F + t] * c0;
    }

    float s = acc;
    #pragma unroll
    for (int o = 16; o; o >>= 1) s += __shfl_xor_sync(0xffffffffu, s, o);
    int lane = t & 31, w = t >> 5;
    if (lane == 0) warpsum[w] = s;
    __syncthreads();
    if (t == 0) {
        float tot = 0.f;
        #pragma unroll
        for (int i = 0; i < NW; i++) tot += warpsum[i];
        bcast = tot / (float)F;
    }
    __syncthreads();
    float mu = bcast;

    float d = acc - mu;
    s = d * d;
    #pragma unroll
    for (int o = 16; o; o >>= 1) s += __shfl_xor_sync(0xffffffffu, s, o);
    __syncthreads();
    if (lane == 0) warpsum[w] = s;
    __syncthreads();
    if (t == 0) {
        float tot = 0.f;
        #pragma unroll
        for (int i = 0; i < NW; i++) tot += warpsum[i];
        bcast = rsqrtf(tot / (float)F + 1e-5f);
    }
    __syncthreads();
    float rstd = bcast;

    float y = d * rstd * g[t] + be[t];
    out[(size_t)node * F + t] = (y > 0.f) ? y : expm1f(y);
}

// ---------------- plain layernorm + elu (head, F=64) ----------------
template <int F>
__global__ void ln_elu_kernel(float* __restrict__ x, const float* __restrict__ g,
                              const float* __restrict__ be) {
    constexpr int NW = F / 32;
    __shared__ float warpsum[NW];
    __shared__ float bcast;
    int node = blockIdx.x;
    float* row = x + (size_t)node * F;
    int t = threadIdx.x;
    float v = row[t];

    float s = v;
    #pragma unroll
    for (int o = 16; o; o >>= 1) s += __shfl_xor_sync(0xffffffffu, s, o);
    int lane = t & 31, w = t >> 5;
    if (lane == 0) warpsum[w] = s;
    __syncthreads();
    if (t == 0) {
        float tot = 0.f;
        #pragma unroll
        for (int i = 0; i < NW; i++) tot += warpsum[i];
        bcast = tot / (float)F;
    }
    __syncthreads();
    float mu = bcast;

    float d = v - mu;
    s = d * d;
    #pragma unroll
    for (int o = 16; o; o >>= 1) s += __shfl_xor_sync(0xffffffffu, s, o);
    __syncthreads();
    if (lane == 0) warpsum[w] = s;
    __syncthreads();
    if (t == 0) {
        float tot = 0.f;
        #pragma unroll
        for (int i = 0; i < NW; i++) tot += warpsum[i];
        bcast = rsqrtf(tot / (float)F + 1e-5f);
    }
    __syncthreads();
    float rstd = bcast;

    float y = d * rstd * g[t] + be[t];
    row[t] = (y > 0.f) ? y : expm1f(y);
}

// ---------------- tf32 tensor-core GEMM: C[M,Nc] = A[M,K] @ W[K,Nc] (+bias) ----------------
// BM=128, BN=64, BK=16; 256 threads = 8 warps; warp tile 32x32 (2x4 m16n8k8 frags).
#define GBM 128
#define GBN 64
#define GBK 16
#define AS_STRIDE 136   // 8*136 mod 32 == 0? 136 mod 32 = 8 -> frag banks 8k+m, conflict-free
#define BS_STRIDE 72    // 72 mod 32 = 8 -> frag banks 8k+n, conflict-free

__device__ __forceinline__ uint32_t f2tf32(float f) {
    uint32_t r;
    asm("cvt.rna.tf32.f32 %0, %1;" : "=r"(r) : "f"(f));
    return r;
}

template <bool BIAS>
__global__ void __launch_bounds__(256) gemm_tf32_kernel(
    const float* __restrict__ A, const float* __restrict__ W,
    const float* __restrict__ bias, float* __restrict__ C,
    int M, int K, int Nc) {
    __shared__ uint32_t As[GBK][AS_STRIDE];
    __shared__ uint32_t Bs[GBK][BS_STRIDE];

    int tid = threadIdx.x;
    int warp = tid >> 5, lane = tid & 31;
    int warpM = warp & 3;        // 4 warps along M
    int warpN = warp >> 2;       // 2 warps along N
    int blockM = blockIdx.y * GBM;
    int blockN = blockIdx.x * GBN;

    float c[2][4][4];
    #pragma unroll
    for (int mi = 0; mi < 2; mi++)
        #pragma unroll
        for (int ni = 0; ni < 4; ni++)
            #pragma unroll
            for (int r = 0; r < 4; r++) c[mi][ni][r] = 0.f;

    // A staging: each thread loads 8 floats of one row
    int arow = tid >> 1;            // 0..127
    int acg  = (tid & 1) << 3;      // 0 or 8
    int aRowG = blockM + arow;
    bool aValid = aRowG < M;
    const float* Aptr = A + (size_t)aRowG * K + acg;
    // B staging: each thread loads one float4
    int brow = tid >> 4;            // 0..15
    int bcol = (tid & 15) << 2;     // 0..60
    bool bValid = (blockN + bcol) < Nc;

    int mrow = lane >> 2;           // 0..7
    int kcol = lane & 3;            // 0..3

    for (int k0 = 0; k0 < K; k0 += GBK) {
        float4 v0 = make_float4(0.f, 0.f, 0.f, 0.f);
        float4 v1 = make_float4(0.f, 0.f, 0.f, 0.f);
        if (aValid) {
            v0 = *reinterpret_cast<const float4*>(Aptr + k0);
            v1 = *reinterpret_cast<const float4*>(Aptr + k0 + 4);
        }
        As[acg + 0][arow] = f2tf32(v0.x);
        As[acg + 1][arow] = f2tf32(v0.y);
        As[acg + 2][arow] = f2tf32(v0.z);
        As[acg + 3][arow] = f2tf32(v0.w);
        As[acg + 4][arow] = f2tf32(v1.x);
        As[acg + 5][arow] = f2tf32(v1.y);
        As[acg + 6][arow] = f2tf32(v1.z);
        As[acg + 7][arow] = f2tf32(v1.w);

        float4 wv = make_float4(0.f, 0.f, 0.f, 0.f);
        if (bValid) wv = *reinterpret_cast<const float4*>(W + (size_t)(k0 + brow) * Nc + blockN + bcol);
        Bs[brow][bcol + 0] = f2tf32(wv.x);
        Bs[brow][bcol + 1] = f2tf32(wv.y);
        Bs[brow][bcol + 2] = f2tf32(wv.z);
        Bs[brow][bcol + 3] = f2tf32(wv.w);
        __syncthreads();

        #pragma unroll
        for (int kk = 0; kk < GBK; kk += 8) {
            uint32_t a[2][4];
            #pragma unroll
            for (int mi = 0; mi < 2; mi++) {
                int r = warpM * 32 + mi * 16 + mrow;
                a[mi][0] = As[kk + kcol][r];
                a[mi][1] = As[kk + kcol][r + 8];
                a[mi][2] = As[kk + kcol + 4][r];
                a[mi][3] = As[kk + kcol + 4][r + 8];
            }
            uint32_t b[4][2];
            #pragma unroll
            for (int ni = 0; ni < 4; ni++) {
                int n = warpN * 32 + ni * 8 + mrow;
                b[ni][0] = Bs[kk + kcol][n];
                b[ni][1] = Bs[kk + kcol + 4][n];
            }
            #pragma unroll
            for (int mi = 0; mi < 2; mi++)
                #pragma unroll
                for (int ni = 0; ni < 4; ni++) {
                    asm volatile(
                        "mma.sync.aligned.m16n8k8.row.col.f32.tf32.tf32.f32 "
                        "{%0,%1,%2,%3}, {%4,%5,%6,%7}, {%8,%9}, {%0,%1,%2,%3};\n"
                        : "+f"(c[mi][ni][0]), "+f"(c[mi][ni][1]),
                          "+f"(c[mi][ni][2]), "+f"(c[mi][ni][3])
                        : "r"(a[mi][0]), "r"(a[mi][1]), "r"(a[mi][2]), "r"(a[mi][3]),
                          "r"(b[ni][0]), "r"(b[ni][1]));
                }
        }
        __syncthreads();
    }

    // store C
    #pragma unroll
    for (int mi = 0; mi < 2; mi++) {
        int r0 = blockM + warpM * 32 + mi * 16 + mrow;
        #pragma unroll
        for (int ni = 0; ni < 4; ni++) {
            int cc = blockN + warpN * 32 + ni * 8 + kcol * 2;
            float bv0 = 0.f, bv1 = 0.f;
            if (BIAS) {
                if (cc < Nc) bv0 = bias[cc];
                if (cc + 1 < Nc) bv1 = bias[cc + 1];
            }
            if (r0 < M) {
                if (cc < Nc)     C[(size_t)r0 * Nc + cc]     = c[mi][ni][0] + bv0;
                if (cc + 1 < Nc) C[(size_t)r0 * Nc + cc + 1] = c[mi][ni][1] + bv1;
            }
            if (r0 + 8 < M) {
                if (cc < Nc)     C[(size_t)(r0 + 8) * Nc + cc]     = c[mi][ni][2] + bv0;
                if (cc + 1 < Nc) C[(size_t)(r0 + 8) * Nc + cc + 1] = c[mi][ni][3] + bv1;
            }
        }
    }
}

static inline void launch_gemm(const float* A, const float* W, const float* bias, float* C,
                               int M, int K, int Nc) {
    dim3 grid((Nc + GBN - 1) / GBN, (M + GBM - 1) / GBM);
    if (bias)
        gemm_tf32_kernel<true><<<grid, 256>>>(A, W, bias, C, M, K, Nc);
    else
        gemm_tf32_kernel<false><<<grid, 256>>>(A, W, nullptr, C, M, K, Nc);
}

extern "C" void kernel_launch(void* const* d_in, const int* in_sizes, int n_in,
                              void* d_out, int out_size) {
    const float* x   = (const float*)d_in[0];
    const int*   ei  = (const int*)d_in[1];
    const float* W1  = (const float*)d_in[2];
    const float* b1  = (const float*)d_in[3];
    const float* g1  = (const float*)d_in[4];
    const float* be1 = (const float*)d_in[5];
    const float* W2  = (const float*)d_in[6];
    const float* b2  = (const float*)d_in[7];
    const float* g2  = (const float*)d_in[8];
    const float* be2 = (const float*)d_in[9];
    const float* W3  = (const float*)d_in[10];
    const float* b3  = (const float*)d_in[11];
    const float* g3  = (const float*)d_in[12];
    const float* be3 = (const float*)d_in[13];
    const float* Wl1 = (const float*)d_in[14];
    const float* bl1 = (const float*)d_in[15];
    const float* g4  = (const float*)d_in[16];
    const float* be4 = (const float*)d_in[17];
    const float* Wl2 = (const float*)d_in[18];
    const float* bl2 = (const float*)d_in[19];
    float* out = (float*)d_out;

    const int N = in_sizes[0] / 128;
    const int E = in_sizes[1] / 2;
    const int* src = ei;
    const int* dst = ei + E;

    float *dinv, *bufA, *bufB, *csr_coef;
    int *cnt, *rowptr, *cursor, *csr_src, *partial;
    cudaGetSymbolAddress((void**)&dinv,     d_dinv);
    cudaGetSymbolAddress((void**)&cnt,      d_cnt);
    cudaGetSymbolAddress((void**)&rowptr,   d_rowptr);
    cudaGetSymbolAddress((void**)&cursor,   d_cursor);
    cudaGetSymbolAddress((void**)&partial,  d_partial);
    cudaGetSymbolAddress((void**)&csr_src,  d_csr_src);
    cudaGetSymbolAddress((void**)&csr_coef, d_csr_coef);
    cudaGetSymbolAddress((void**)&bufA,     d_bufA);
    cudaGetSymbolAddress((void**)&bufB,     d_bufB);

    // ---- CSR build ----
    int nBlocks = (N + SCAN_BLK - 1) / SCAN_BLK;
    zero_cnt_kernel<<<(N + 255) / 256, 256>>>(cnt, N);
    count_kernel<<<(E + 255) / 256, 256>>>(dst, cnt, E);
    dinv_kernel<<<(N + 255) / 256, 256>>>(cnt, dinv, N);
    block_reduce_kernel<<<nBlocks, SCAN_BLK>>>(cnt, partial, N);
    scan_partials_kernel<<<1, SCAN_BLK>>>(partial, nBlocks);
    scan_final_kernel<<<nBlocks, SCAN_BLK>>>(cnt, partial, rowptr, cursor, N);
    fill_kernel<<<(E + 255) / 256, 256>>>(src, dst, dinv, cursor, csr_src, csr_coef, E);

    // ---- layer 1: gemm -> fused gather+LN+ELU (F = 128)
    launch_gemm(x, W1, nullptr, bufA, N, 128, 128);
    gather_ln_kernel<128><<<N, 128>>>(bufA, rowptr, csr_src, csr_coef, dinv, b1, g1, be1, bufB);

    // ---- layer 2 (F = 256)
    launch_gemm(bufB, W2, nullptr, bufA, N, 128, 256);
    gather_ln_kernel<256><<<N, 256>>>(bufA, rowptr, csr_src, csr_coef, dinv, b2, g2, be2, bufB);

    // ---- layer 3 (F = 128)
    launch_gemm(bufB, W3, nullptr, bufA, N, 256, 128);
    gather_ln_kernel<128><<<N, 128>>>(bufA, rowptr, csr_src, csr_coef, dinv, b3, g3, be3, bufB);

    // ---- head: linear -> LN -> ELU -> linear
    launch_gemm(bufB, Wl1, bl1, bufA, N, 128, 64);
    ln_elu_kernel<64><<<N, 64>>>(bufA, g4, be4);
    launch_gemm(bufA, Wl2, bl2, out, N, 64, 500);
}

// round 8
// speedup vs baseline: 3.8370x; 1.4620x over previous
#include <cuda_runtime.h>
#include <cuda_bf16.h>
#include <math.h>
#include <stdint.h>

// ---------------- problem constants ----------------
#define MAXN 50000
#define MAXE 800000
#define MAXF 256
#define SCAN_BLK 256
#define MAX_PARTIALS 256

// ---------------- device scratch ----------------
__device__ float d_dinv[MAXN];
__device__ int   d_cnt[MAXN];
__device__ int   d_rowptr[MAXN + 1];
__device__ int   d_cursor[MAXN];
__device__ int   d_partial[MAX_PARTIALS];
__device__ int   d_csr_src[MAXE];
__device__ float d_csr_coef[MAXE];
__device__ float d_bufA[(size_t)MAXN * MAXF];
__device__ float d_bufB[(size_t)MAXN * MAXF];

// ---------------- CSR construction ----------------
__global__ void count_kernel(const int* __restrict__ dst, int* __restrict__ cnt, int e) {
    int i = blockIdx.x * blockDim.x + threadIdx.x;
    if (i < e) atomicAdd(&cnt[dst[i]], 1);
}

__global__ void block_reduce_kernel(const int* __restrict__ cnt, int* __restrict__ partial, int n) {
    __shared__ int ws[8];
    int i = blockIdx.x * SCAN_BLK + threadIdx.x;
    int v = (i < n) ? cnt[i] : 0;
    #pragma unroll
    for (int o = 16; o; o >>= 1) v += __shfl_xor_sync(0xffffffffu, v, o);
    int lane = threadIdx.x & 31, w = threadIdx.x >> 5;
    if (lane == 0) ws[w] = v;
    __syncthreads();
    if (threadIdx.x == 0) {
        int s = 0;
        #pragma unroll
        for (int k = 0; k < 8; k++) s += ws[k];
        partial[blockIdx.x] = s;
    }
}

__global__ void scan_partials_kernel(int* __restrict__ partial, int nb) {
    __shared__ int ws[8];
    int t = threadIdx.x;
    int v = (t < nb) ? partial[t] : 0;
    int lane = t & 31, w = t >> 5;
    int x = v;
    #pragma unroll
    for (int o = 1; o < 32; o <<= 1) {
        int y = __shfl_up_sync(0xffffffffu, x, o);
        if (lane >= o) x += y;
    }
    if (lane == 31) ws[w] = x;
    __syncthreads();
    if (w == 0 && lane < 8) {
        int s = ws[lane];
        #pragma unroll
        for (int o = 1; o < 8; o <<= 1) {
            int y = __shfl_up_sync(0xffu, s, o);
            if (lane >= o) s += y;
        }
        ws[lane] = s;
    }
    __syncthreads();
    int incl = x + (w ? ws[w - 1] : 0);
    if (t < nb) partial[t] = incl - v;
}

// per-block scan + offset -> rowptr, cursor; also dinv
__global__ void scan_final_kernel(const int* __restrict__ cnt, const int* __restrict__ partial,
                                  int* __restrict__ rowptr, int* __restrict__ cursor,
                                  float* __restrict__ dinv, int n) {
    __shared__ int ws[8];
    int i = blockIdx.x * SCAN_BLK + threadIdx.x;
    int t = threadIdx.x;
    int v = (i < n) ? cnt[i] : 0;
    int lane = t & 31, w = t >> 5;
    int x = v;
    #pragma unroll
    for (int o = 1; o < 32; o <<= 1) {
        int y = __shfl_up_sync(0xffffffffu, x, o);
        if (lane >= o) x += y;
    }
    if (lane == 31) ws[w] = x;
    __syncthreads();
    if (w == 0 && lane < 8) {
        int s = ws[lane];
        #pragma unroll
        for (int o = 1; o < 8; o <<= 1) {
            int y = __shfl_up_sync(0xffu, s, o);
            if (lane >= o) s += y;
        }
        ws[lane] = s;
    }
    __syncthreads();
    int incl = x + (w ? ws[w - 1] : 0) + partial[blockIdx.x];
    if (i < n) {
        int excl = incl - v;
        rowptr[i] = excl;
        cursor[i] = excl;
        dinv[i] = rsqrtf((float)v + 1.0f);
        if (i == n - 1) rowptr[n] = incl;
    }
}

__global__ void fill_kernel(const int* __restrict__ src, const int* __restrict__ dst,
                            const float* __restrict__ dinv, int* __restrict__ cursor,
                            int* __restrict__ csr_src, float* __restrict__ csr_coef, int e) {
    int i = blockIdx.x * blockDim.x + threadIdx.x;
    if (i >= e) return;
    int s = src[i], d = dst[i];
    int pos = atomicAdd(&cursor[d], 1);
    csr_src[pos] = s;
    csr_coef[pos] = dinv[s] * dinv[d];
}

// ---------------- warp-per-node gather (+ optional bias/LN/ELU) ----------------
__device__ __forceinline__ float4 f4fma(float4 a, float c, float4 acc) {
    acc.x += a.x * c; acc.y += a.y * c; acc.z += a.z * c; acc.w += a.w * c;
    return acc;
}

template <int F, bool LN>
__global__ void __launch_bounds__(256) gather_warp_kernel(
    const float* __restrict__ h,
    const int* __restrict__ rowptr,
    const int* __restrict__ csr_src,
    const float* __restrict__ csr_coef,
    const float* __restrict__ dinv,
    const float* __restrict__ bias,
    const float* __restrict__ g,
    const float* __restrict__ be,
    float* __restrict__ out, int n) {
    constexpr int RS = F / 4;          // row stride in float4
    constexpr int V  = F / 128;        // float4 per lane (1 or 2)
    int warp = threadIdx.x >> 5, lane = threadIdx.x & 31;
    int node = blockIdx.x * 8 + warp;
    if (node >= n) return;

    const float4* h4 = reinterpret_cast<const float4*>(h);
    float4* out4 = reinterpret_cast<float4*>(out);

    float di = dinv[node];
    float dsq = di * di;
    float4 acc[V];
    #pragma unroll
    for (int v = 0; v < V; v++) {
        float4 hv = h4[(size_t)node * RS + lane + v * 32];
        acc[v].x = hv.x * dsq; acc[v].y = hv.y * dsq;
        acc[v].z = hv.z * dsq; acc[v].w = hv.w * dsq;
        if (LN) {
            float4 bv = reinterpret_cast<const float4*>(bias)[lane + v * 32];
            acc[v].x += bv.x; acc[v].y += bv.y; acc[v].z += bv.z; acc[v].w += bv.w;
        }
    }

    int e = rowptr[node], end = rowptr[node + 1];
    for (; e + 3 < end; e += 4) {
        int s0 = __ldg(&csr_src[e]),     s1 = __ldg(&csr_src[e + 1]);
        int s2 = __ldg(&csr_src[e + 2]), s3 = __ldg(&csr_src[e + 3]);
        float c0 = __ldg(&csr_coef[e]),     c1 = __ldg(&csr_coef[e + 1]);
        float c2 = __ldg(&csr_coef[e + 2]), c3 = __ldg(&csr_coef[e + 3]);
        #pragma unroll
        for (int v = 0; v < V; v++) {
            float4 v0 = h4[(size_t)s0 * RS + lane + v * 32];
            float4 v1 = h4[(size_t)s1 * RS + lane + v * 32];
            float4 v2 = h4[(size_t)s2 * RS + lane + v * 32];
            float4 v3 = h4[(size_t)s3 * RS + lane + v * 32];
            acc[v] = f4fma(v0, c0, acc[v]);
            acc[v] = f4fma(v1, c1, acc[v]);
            acc[v] = f4fma(v2, c2, acc[v]);
            acc[v] = f4fma(v3, c3, acc[v]);
        }
    }
    for (; e < end; e++) {
        int s0 = __ldg(&csr_src[e]);
        float c0 = __ldg(&csr_coef[e]);
        #pragma unroll
        for (int v = 0; v < V; v++)
            acc[v] = f4fma(h4[(size_t)s0 * RS + lane + v * 32], c0, acc[v]);
    }

    if (!LN) {
        #pragma unroll
        for (int v = 0; v < V; v++) out4[(size_t)node * RS + lane + v * 32] = acc[v];
        return;
    }

    // warp LayerNorm + ELU
    float s = 0.f;
    #pragma unroll
    for (int v = 0; v < V; v++) s += acc[v].x + acc[v].y + acc[v].z + acc[v].w;
    #pragma unroll
    for (int o = 16; o; o >>= 1) s += __shfl_xor_sync(0xffffffffu, s, o);
    float mu = s / (float)F;

    float var = 0.f;
    #pragma unroll
    for (int v = 0; v < V; v++) {
        float dx = acc[v].x - mu, dy = acc[v].y - mu, dz = acc[v].z - mu, dw = acc[v].w - mu;
        var += dx * dx + dy * dy + dz * dz + dw * dw;
    }
    #pragma unroll
    for (int o = 16; o; o >>= 1) var += __shfl_xor_sync(0xffffffffu, var, o);
    float rstd = rsqrtf(var / (float)F + 1e-5f);

    #pragma unroll
    for (int v = 0; v < V; v++) {
        float4 gv = reinterpret_cast<const float4*>(g)[lane + v * 32];
        float4 bv = reinterpret_cast<const float4*>(be)[lane + v * 32];
        float4 r;
        r.x = (acc[v].x - mu) * rstd * gv.x + bv.x;
        r.y = (acc[v].y - mu) * rstd * gv.y + bv.y;
        r.z = (acc[v].z - mu) * rstd * gv.z + bv.z;
        r.w = (acc[v].w - mu) * rstd * gv.w + bv.w;
        r.x = (r.x > 0.f) ? r.x : expm1f(r.x);
        r.y = (r.y > 0.f) ? r.y : expm1f(r.y);
        r.z = (r.z > 0.f) ? r.z : expm1f(r.z);
        r.w = (r.w > 0.f) ? r.w : expm1f(r.w);
        out4[(size_t)node * RS + lane + v * 32] = r;
    }
}

// ---------------- warp-per-node LN + ELU (in place) ----------------
template <int F>
__global__ void __launch_bounds__(256) ln_elu_warp_kernel(
    float* __restrict__ x, const float* __restrict__ g, const float* __restrict__ be, int n) {
    constexpr int RS = F / 4;
    constexpr int V  = (F + 127) / 128;      // float4 per lane
    int warp = threadIdx.x >> 5, lane = threadIdx.x & 31;
    int node = blockIdx.x * 8 + warp;
    if (node >= n) return;
    float4* x4 = reinterpret_cast<float4*>(x);

    float4 acc[V];
    bool act[V];
    #pragma unroll
    for (int v = 0; v < V; v++) {
        int idx = lane + v * 32;
        act[v] = idx < RS;
        acc[v] = act[v] ? x4[(size_t)node * RS + idx] : make_float4(0.f, 0.f, 0.f, 0.f);
    }

    float s = 0.f;
    #pragma unroll
    for (int v = 0; v < V; v++) s += acc[v].x + acc[v].y + acc[v].z + acc[v].w;
    #pragma unroll
    for (int o = 16; o; o >>= 1) s += __shfl_xor_sync(0xffffffffu, s, o);
    float mu = s / (float)F;

    float var = 0.f;
    #pragma unroll
    for (int v = 0; v < V; v++) {
        if (!act[v]) continue;
        float dx = acc[v].x - mu, dy = acc[v].y - mu, dz = acc[v].z - mu, dw = acc[v].w - mu;
        var += dx * dx + dy * dy + dz * dz + dw * dw;
    }
    #pragma unroll
    for (int o = 16; o; o >>= 1) var += __shfl_xor_sync(0xffffffffu, var, o);
    float rstd = rsqrtf(var / (float)F + 1e-5f);

    #pragma unroll
    for (int v = 0; v < V; v++) {
        if (!act[v]) continue;
        int idx = lane + v * 32;
        float4 gv = reinterpret_cast<const float4*>(g)[idx];
        float4 bv = reinterpret_cast<const float4*>(be)[idx];
        float4 r;
        r.x = (acc[v].x - mu) * rstd * gv.x + bv.x;
        r.y = (acc[v].y - mu) * rstd * gv.y + bv.y;
        r.z = (acc[v].z - mu) * rstd * gv.z + bv.z;
        r.w = (acc[v].w - mu) * rstd * gv.w + bv.w;
        r.x = (r.x > 0.f) ? r.x : expm1f(r.x);
        r.y = (r.y > 0.f) ? r.y : expm1f(r.y);
        r.z = (r.z > 0.f) ? r.z : expm1f(r.z);
        r.w = (r.w > 0.f) ? r.w : expm1f(r.w);
        x4[(size_t)node * RS + idx] = r;
    }
}

// ---------------- tf32 tensor-core GEMM with double buffering ----------------
#define GBM 128
#define GBN 64
#define GBK 16
#define AS_STRIDE 136
#define BS_STRIDE 72

__device__ __forceinline__ uint32_t f2tf32(float f) {
    uint32_t r;
    asm("cvt.rna.tf32.f32 %0, %1;" : "=r"(r) : "f"(f));
    return r;
}

template <bool BIAS>
__global__ void __launch_bounds__(256) gemm_tf32_kernel(
    const float* __restrict__ A, const float* __restrict__ W,
    const float* __restrict__ bias, float* __restrict__ C,
    int M, int K, int Nc) {
    __shared__ uint32_t As[2][GBK][AS_STRIDE];
    __shared__ uint32_t Bs[2][GBK][BS_STRIDE];

    int tid = threadIdx.x;
    int warp = tid >> 5, lane = tid & 31;
    int warpM = warp & 3;
    int warpN = warp >> 2;
    int blockM = blockIdx.y * GBM;
    int blockN = blockIdx.x * GBN;

    float c[2][4][4];
    #pragma unroll
    for (int mi = 0; mi < 2; mi++)
        #pragma unroll
        for (int ni = 0; ni < 4; ni++)
            #pragma unroll
            for (int r = 0; r < 4; r++) c[mi][ni][r] = 0.f;

    int arow = tid >> 1;
    int acg  = (tid & 1) << 3;
    int aRowG = blockM + arow;
    bool aValid = aRowG < M;
    const float* Aptr = A + (size_t)aRowG * K + acg;
    int brow = tid >> 4;
    int bcol = (tid & 15) << 2;
    bool bValid = (blockN + bcol) < Nc;

    int mrow = lane >> 2;
    int kcol = lane & 3;

    // prologue: load tile 0 into buffer 0
    {
        float4 v0 = make_float4(0.f, 0.f, 0.f, 0.f);
        float4 v1 = make_float4(0.f, 0.f, 0.f, 0.f);
        if (aValid) {
            v0 = *reinterpret_cast<const float4*>(Aptr);
            v1 = *reinterpret_cast<const float4*>(Aptr + 4);
        }
        As[0][acg + 0][arow] = f2tf32(v0.x);
        As[0][acg + 1][arow] = f2tf32(v0.y);
        As[0][acg + 2][arow] = f2tf32(v0.z);
        As[0][acg + 3][arow] = f2tf32(v0.w);
        As[0][acg + 4][arow] = f2tf32(v1.x);
        As[0][acg + 5][arow] = f2tf32(v1.y);
        As[0][acg + 6][arow] = f2tf32(v1.z);
        As[0][acg + 7][arow] = f2tf32(v1.w);
        float4 wv = make_float4(0.f, 0.f, 0.f, 0.f);
        if (bValid) wv = *reinterpret_cast<const float4*>(W + (size_t)brow * Nc + blockN + bcol);
        Bs[0][brow][bcol + 0] = f2tf32(wv.x);
        Bs[0][brow][bcol + 1] = f2tf32(wv.y);
        Bs[0][brow][bcol + 2] = f2tf32(wv.z);
        Bs[0][brow][bcol + 3] = f2tf32(wv.w);
    }
    __syncthreads();

    int buf = 0;
    for (int k0 = 0; k0 < K; k0 += GBK) {
        bool nxt = (k0 + GBK) < K;
        float4 v0n, v1n, wvn;
        if (nxt) {
            v0n = make_float4(0.f, 0.f, 0.f, 0.f);
            v1n = make_float4(0.f, 0.f, 0.f, 0.f);
            if (aValid) {
                v0n = *reinterpret_cast<const float4*>(Aptr + k0 + GBK);
                v1n = *reinterpret_cast<const float4*>(Aptr + k0 + GBK + 4);
            }
            wvn = make_float4(0.f, 0.f, 0.f, 0.f);
            if (bValid) wvn = *reinterpret_cast<const float4*>(W + (size_t)(k0 + GBK + brow) * Nc + blockN + bcol);
        }

        #pragma unroll
        for (int kk = 0; kk < GBK; kk += 8) {
            uint32_t a[2][4];
            #pragma unroll
            for (int mi = 0; mi < 2; mi++) {
                int r = warpM * 32 + mi * 16 + mrow;
                a[mi][0] = As[buf][kk + kcol][r];
                a[mi][1] = As[buf][kk + kcol][r + 8];
                a[mi][2] = As[buf][kk + kcol + 4][r];
                a[mi][3] = As[buf][kk + kcol + 4][r + 8];
            }
            uint32_t b[4][2];
            #pragma unroll
            for (int ni = 0; ni < 4; ni++) {
                int n = warpN * 32 + ni * 8 + mrow;
                b[ni][0] = Bs[buf][kk + kcol][n];
                b[ni][1] = Bs[buf][kk + kcol + 4][n];
            }
            #pragma unroll
            for (int mi = 0; mi < 2; mi++)
                #pragma unroll
                for (int ni = 0; ni < 4; ni++) {
                    asm volatile(
                        "mma.sync.aligned.m16n8k8.row.col.f32.tf32.tf32.f32 "
                        "{%0,%1,%2,%3}, {%4,%5,%6,%7}, {%8,%9}, {%0,%1,%2,%3};\n"
                        : "+f"(c[mi][ni][0]), "+f"(c[mi][ni][1]),
                          "+f"(c[mi][ni][2]), "+f"(c[mi][ni][3])
                        : "r"(a[mi][0]), "r"(a[mi][1]), "r"(a[mi][2]), "r"(a[mi][3]),
                          "r"(b[ni][0]), "r"(b[ni][1]));
                }
        }

        if (nxt) {
            int nb = buf ^ 1;
            As[nb][acg + 0][arow] = f2tf32(v0n.x);
            As[nb][acg + 1][arow] = f2tf32(v0n.y);
            As[nb][acg + 2][arow] = f2tf32(v0n.z);
            As[nb][acg + 3][arow] = f2tf32(v0n.w);
            As[nb][acg + 4][arow] = f2tf32(v1n.x);
            As[nb][acg + 5][arow] = f2tf32(v1n.y);
            As[nb][acg + 6][arow] = f2tf32(v1n.z);
            As[nb][acg + 7][arow] = f2tf32(v1n.w);
            Bs[nb][brow][bcol + 0] = f2tf32(wvn.x);
            Bs[nb][brow][bcol + 1] = f2tf32(wvn.y);
            Bs[nb][brow][bcol + 2] = f2tf32(wvn.z);
            Bs[nb][brow][bcol + 3] = f2tf32(wvn.w);
            __syncthreads();
            buf = nb;
        }
    }

    #pragma unroll
    for (int mi = 0; mi < 2; mi++) {
        int r0 = blockM + warpM * 32 + mi * 16 + mrow;
        #pragma unroll
        for (int ni = 0; ni < 4; ni++) {
            int cc = blockN + warpN * 32 + ni * 8 + kcol * 2;
            float bv0 = 0.f, bv1 = 0.f;
            if (BIAS) {
                if (cc < Nc) bv0 = bias[cc];
                if (cc + 1 < Nc) bv1 = bias[cc + 1];
            }
            if (r0 < M) {
                if (cc < Nc)     C[(size_t)r0 * Nc + cc]     = c[mi][ni][0] + bv0;
                if (cc + 1 < Nc) C[(size_t)r0 * Nc + cc + 1] = c[mi][ni][1] + bv1;
            }
            if (r0 + 8 < M) {
                if (cc < Nc)     C[(size_t)(r0 + 8) * Nc + cc]     = c[mi][ni][2] + bv0;
                if (cc + 1 < Nc) C[(size_t)(r0 + 8) * Nc + cc + 1] = c[mi][ni][3] + bv1;
            }
        }
    }
}

static inline void launch_gemm(const float* A, const float* W, const float* bias, float* C,
                               int M, int K, int Nc) {
    dim3 grid((Nc + GBN - 1) / GBN, (M + GBM - 1) / GBM);
    if (bias)
        gemm_tf32_kernel<true><<<grid, 256>>>(A, W, bias, C, M, K, Nc);
    else
        gemm_tf32_kernel<false><<<grid, 256>>>(A, W, nullptr, C, M, K, Nc);
}

extern "C" void kernel_launch(void* const* d_in, const int* in_sizes, int n_in,
                              void* d_out, int out_size) {
    const float* x   = (const float*)d_in[0];
    const int*   ei  = (const int*)d_in[1];
    const float* W1  = (const float*)d_in[2];
    const float* b1  = (const float*)d_in[3];
    const float* g1  = (const float*)d_in[4];
    const float* be1 = (const float*)d_in[5];
    const float* W2  = (const float*)d_in[6];
    const float* b2  = (const float*)d_in[7];
    const float* g2  = (const float*)d_in[8];
    const float* be2 = (const float*)d_in[9];
    const float* W3  = (const float*)d_in[10];
    const float* b3  = (const float*)d_in[11];
    const float* g3  = (const float*)d_in[12];
    const float* be3 = (const float*)d_in[13];
    const float* Wl1 = (const float*)d_in[14];
    const float* bl1 = (const float*)d_in[15];
    const float* g4  = (const float*)d_in[16];
    const float* be4 = (const float*)d_in[17];
    const float* Wl2 = (const float*)d_in[18];
    const float* bl2 = (const float*)d_in[19];
    float* out = (float*)d_out;

    const int N = in_sizes[0] / 128;
    const int E = in_sizes[1] / 2;
    const int* src = ei;
    const int* dst = ei + E;

    float *dinv, *bufA, *bufB, *csr_coef;
    int *cnt, *rowptr, *cursor, *csr_src, *partial;
    cudaGetSymbolAddress((void**)&dinv,     d_dinv);
    cudaGetSymbolAddress((void**)&cnt,      d_cnt);
    cudaGetSymbolAddress((void**)&rowptr,   d_rowptr);
    cudaGetSymbolAddress((void**)&cursor,   d_cursor);
    cudaGetSymbolAddress((void**)&partial,  d_partial);
    cudaGetSymbolAddress((void**)&csr_src,  d_csr_src);
    cudaGetSymbolAddress((void**)&csr_coef, d_csr_coef);
    cudaGetSymbolAddress((void**)&bufA,     d_bufA);
    cudaGetSymbolAddress((void**)&bufB,     d_bufB);

    // ---- CSR build ----
    int nBlocks = (N + SCAN_BLK - 1) / SCAN_BLK;
    cudaMemsetAsync(cnt, 0, (size_t)N * sizeof(int));
    count_kernel<<<(E + 255) / 256, 256>>>(dst, cnt, E);
    block_reduce_kernel<<<nBlocks, SCAN_BLK>>>(cnt, partial, N);
    scan_partials_kernel<<<1, SCAN_BLK>>>(partial, nBlocks);
    scan_final_kernel<<<nBlocks, SCAN_BLK>>>(cnt, partial, rowptr, cursor, dinv, N);
    fill_kernel<<<(E + 255) / 256, 256>>>(src, dst, dinv, cursor, csr_src, csr_coef, E);

    int gatherGrid = (N + 7) / 8;

    // ---- layer 1 (128->128): gemm -> gather+LN+ELU
    launch_gemm(x, W1, nullptr, bufA, N, 128, 128);
    gather_warp_kernel<128, true><<<gatherGrid, 256>>>(bufA, rowptr, csr_src, csr_coef,
                                                       dinv, b1, g1, be1, bufB, N);

    // ---- layer 2 (128->256): aggregate FIRST (gather at 128), then gemm(+bias), then LN
    gather_warp_kernel<128, false><<<gatherGrid, 256>>>(bufB, rowptr, csr_src, csr_coef,
                                                        dinv, nullptr, nullptr, nullptr, bufA, N);
    launch_gemm(bufA, W2, b2, bufB, N, 128, 256);
    ln_elu_warp_kernel<256><<<gatherGrid, 256>>>(bufB, g2, be2, N);

    // ---- layer 3 (256->128): gemm -> gather+LN+ELU
    launch_gemm(bufB, W3, nullptr, bufA, N, 256, 128);
    gather_warp_kernel<128, true><<<gatherGrid, 256>>>(bufA, rowptr, csr_src, csr_coef,
                                                       dinv, b3, g3, be3, bufB, N);

    // ---- head: linear -> LN -> ELU -> linear
    launch_gemm(bufB, Wl1, bl1, bufA, N, 128, 64);
    ln_elu_warp_kernel<64><<<gatherGrid, 256>>>(bufA, g4, be4, N);
    launch_gemm(bufA, Wl2, bl2, out, N, 64, 500);
}

// round 10
// speedup vs baseline: 3.9877x; 1.0393x over previous
#include <cuda_runtime.h>
#include <cuda_bf16.h>
#include <math.h>
#include <stdint.h>

// ---------------- problem constants ----------------
#define MAXN 50000
#define MAXE 800000
#define MAXF 256
#define SCAN_BLK 256
#define MAX_PARTIALS 256

// ---------------- device scratch ----------------
__device__ float d_dinv[MAXN];
__device__ int   d_cnt[MAXN];
__device__ int   d_rowptr[MAXN + 1];
__device__ int   d_cursor[MAXN];
__device__ int   d_partial[MAX_PARTIALS];
__device__ int   d_csr_src[MAXE];
__device__ float d_csr_coef[MAXE];
__device__ float d_bufA[(size_t)MAXN * MAXF];
__device__ float d_bufB[(size_t)MAXN * MAXF];

// ---------------- CSR construction ----------------
__global__ void count_kernel(const int* __restrict__ dst, int* __restrict__ cnt, int e) {
    int i = blockIdx.x * blockDim.x + threadIdx.x;
    if (i < e) atomicAdd(&cnt[dst[i]], 1);
}

__global__ void block_reduce_kernel(const int* __restrict__ cnt, int* __restrict__ partial, int n) {
    __shared__ int ws[8];
    int i = blockIdx.x * SCAN_BLK + threadIdx.x;
    int v = (i < n) ? cnt[i] : 0;
    #pragma unroll
    for (int o = 16; o; o >>= 1) v += __shfl_xor_sync(0xffffffffu, v, o);
    int lane = threadIdx.x & 31, w = threadIdx.x >> 5;
    if (lane == 0) ws[w] = v;
    __syncthreads();
    if (threadIdx.x == 0) {
        int s = 0;
        #pragma unroll
        for (int k = 0; k < 8; k++) s += ws[k];
        partial[blockIdx.x] = s;
    }
}

__global__ void scan_partials_kernel(int* __restrict__ partial, int nb) {
    __shared__ int ws[8];
    int t = threadIdx.x;
    int v = (t < nb) ? partial[t] : 0;
    int lane = t & 31, w = t >> 5;
    int x = v;
    #pragma unroll
    for (int o = 1; o < 32; o <<= 1) {
        int y = __shfl_up_sync(0xffffffffu, x, o);
        if (lane >= o) x += y;
    }
    if (lane == 31) ws[w] = x;
    __syncthreads();
    if (w == 0 && lane < 8) {
        int s = ws[lane];
        #pragma unroll
        for (int o = 1; o < 8; o <<= 1) {
            int y = __shfl_up_sync(0xffu, s, o);
            if (lane >= o) s += y;
        }
        ws[lane] = s;
    }
    __syncthreads();
    int incl = x + (w ? ws[w - 1] : 0);
    if (t < nb) partial[t] = incl - v;
}

__global__ void scan_final_kernel(const int* __restrict__ cnt, const int* __restrict__ partial,
                                  int* __restrict__ rowptr, int* __restrict__ cursor,
                                  float* __restrict__ dinv, int n) {
    __shared__ int ws[8];
    int i = blockIdx.x * SCAN_BLK + threadIdx.x;
    int t = threadIdx.x;
    int v = (i < n) ? cnt[i] : 0;
    int lane = t & 31, w = t >> 5;
    int x = v;
    #pragma unroll
    for (int o = 1; o < 32; o <<= 1) {
        int y = __shfl_up_sync(0xffffffffu, x, o);
        if (lane >= o) x += y;
    }
    if (lane == 31) ws[w] = x;
    __syncthreads();
    if (w == 0 && lane < 8) {
        int s = ws[lane];
        #pragma unroll
        for (int o = 1; o < 8; o <<= 1) {
            int y = __shfl_up_sync(0xffu, s, o);
            if (lane >= o) s += y;
        }
        ws[lane] = s;
    }
    __syncthreads();
    int incl = x + (w ? ws[w - 1] : 0) + partial[blockIdx.x];
    if (i < n) {
        int excl = incl - v;
        rowptr[i] = excl;
        cursor[i] = excl;
        dinv[i] = rsqrtf((float)v + 1.0f);
        if (i == n - 1) rowptr[n] = incl;
    }
}

__global__ void fill_kernel(const int* __restrict__ src, const int* __restrict__ dst,
                            const float* __restrict__ dinv, int* __restrict__ cursor,
                            int* __restrict__ csr_src, float* __restrict__ csr_coef, int e) {
    int i = blockIdx.x * blockDim.x + threadIdx.x;
    if (i >= e) return;
    int s = src[i], d = dst[i];
    int pos = atomicAdd(&cursor[d], 1);
    csr_src[pos] = s;
    csr_coef[pos] = dinv[s] * dinv[d];
}

// ---------------- warp-per-node gather (+ optional bias/LN/ELU) ----------------
__device__ __forceinline__ float4 f4fma(float4 a, float c, float4 acc) {
    acc.x += a.x * c; acc.y += a.y * c; acc.z += a.z * c; acc.w += a.w * c;
    return acc;
}

template <int F, bool LN>
__global__ void __launch_bounds__(256) gather_warp_kernel(
    const float* __restrict__ h,
    const int* __restrict__ rowptr,
    const int* __restrict__ csr_src,
    const float* __restrict__ csr_coef,
    const float* __restrict__ dinv,
    const float* __restrict__ bias,
    const float* __restrict__ g,
    const float* __restrict__ be,
    float* __restrict__ out, int n) {
    constexpr int RS = F / 4;
    constexpr int V  = F / 128;
    int warp = threadIdx.x >> 5, lane = threadIdx.x & 31;
    int node = blockIdx.x * 8 + warp;
    if (node >= n) return;

    const float4* h4 = reinterpret_cast<const float4*>(h);
    float4* out4 = reinterpret_cast<float4*>(out);

    float di = dinv[node];
    float dsq = di * di;
    float4 acc[V];
    #pragma unroll
    for (int v = 0; v < V; v++) {
        float4 hv = h4[(size_t)node * RS + lane + v * 32];
        acc[v].x = hv.x * dsq; acc[v].y = hv.y * dsq;
        acc[v].z = hv.z * dsq; acc[v].w = hv.w * dsq;
        if (LN) {
            float4 bv = reinterpret_cast<const float4*>(bias)[lane + v * 32];
            acc[v].x += bv.x; acc[v].y += bv.y; acc[v].z += bv.z; acc[v].w += bv.w;
        }
    }

    int e = rowptr[node], end = rowptr[node + 1];
    for (; e + 3 < end; e += 4) {
        int s0 = __ldg(&csr_src[e]),     s1 = __ldg(&csr_src[e + 1]);
        int s2 = __ldg(&csr_src[e + 2]), s3 = __ldg(&csr_src[e + 3]);
        float c0 = __ldg(&csr_coef[e]),     c1 = __ldg(&csr_coef[e + 1]);
        float c2 = __ldg(&csr_coef[e + 2]), c3 = __ldg(&csr_coef[e + 3]);
        #pragma unroll
        for (int v = 0; v < V; v++) {
            float4 v0 = h4[(size_t)s0 * RS + lane + v * 32];
            float4 v1 = h4[(size_t)s1 * RS + lane + v * 32];
            float4 v2 = h4[(size_t)s2 * RS + lane + v * 32];
            float4 v3 = h4[(size_t)s3 * RS + lane + v * 32];
            acc[v] = f4fma(v0, c0, acc[v]);
            acc[v] = f4fma(v1, c1, acc[v]);
            acc[v] = f4fma(v2, c2, acc[v]);
            acc[v] = f4fma(v3, c3, acc[v]);
        }
    }
    for (; e < end; e++) {
        int s0 = __ldg(&csr_src[e]);
        float c0 = __ldg(&csr_coef[e]);
        #pragma unroll
        for (int v = 0; v < V; v++)
            acc[v] = f4fma(h4[(size_t)s0 * RS + lane + v * 32], c0, acc[v]);
    }

    if (!LN) {
        #pragma unroll
        for (int v = 0; v < V; v++) out4[(size_t)node * RS + lane + v * 32] = acc[v];
        return;
    }

    float s = 0.f;
    #pragma unroll
    for (int v = 0; v < V; v++) s += acc[v].x + acc[v].y + acc[v].z + acc[v].w;
    #pragma unroll
    for (int o = 16; o; o >>= 1) s += __shfl_xor_sync(0xffffffffu, s, o);
    float mu = s / (float)F;

    float var = 0.f;
    #pragma unroll
    for (int v = 0; v < V; v++) {
        float dx = acc[v].x - mu, dy = acc[v].y - mu, dz = acc[v].z - mu, dw = acc[v].w - mu;
        var += dx * dx + dy * dy + dz * dz + dw * dw;
    }
    #pragma unroll
    for (int o = 16; o; o >>= 1) var += __shfl_xor_sync(0xffffffffu, var, o);
    float rstd = rsqrtf(var / (float)F + 1e-5f);

    #pragma unroll
    for (int v = 0; v < V; v++) {
        float4 gv = reinterpret_cast<const float4*>(g)[lane + v * 32];
        float4 bv = reinterpret_cast<const float4*>(be)[lane + v * 32];
        float4 r;
        r.x = (acc[v].x - mu) * rstd * gv.x + bv.x;
        r.y = (acc[v].y - mu) * rstd * gv.y + bv.y;
        r.z = (acc[v].z - mu) * rstd * gv.z + bv.z;
        r.w = (acc[v].w - mu) * rstd * gv.w + bv.w;
        r.x = (r.x > 0.f) ? r.x : expm1f(r.x);
        r.y = (r.y > 0.f) ? r.y : expm1f(r.y);
        r.z = (r.z > 0.f) ? r.z : expm1f(r.z);
        r.w = (r.w > 0.f) ? r.w : expm1f(r.w);
        out4[(size_t)node * RS + lane + v * 32] = r;
    }
}

// ---------------- warp-per-node LN + ELU (in place) ----------------
template <int F>
__global__ void __launch_bounds__(256) ln_elu_warp_kernel(
    float* __restrict__ x, const float* __restrict__ g, const float* __restrict__ be, int n) {
    constexpr int RS = F / 4;
    constexpr int V  = (F + 127) / 128;
    int warp = threadIdx.x >> 5, lane = threadIdx.x & 31;
    int node = blockIdx.x * 8 + warp;
    if (node >= n) return;
    float4* x4 = reinterpret_cast<float4*>(x);

    float4 acc[V];
    bool act[V];
    #pragma unroll
    for (int v = 0; v < V; v++) {
        int idx = lane + v * 32;
        act[v] = idx < RS;
        acc[v] = act[v] ? x4[(size_t)node * RS + idx] : make_float4(0.f, 0.f, 0.f, 0.f);
    }

    float s = 0.f;
    #pragma unroll
    for (int v = 0; v < V; v++) s += acc[v].x + acc[v].y + acc[v].z + acc[v].w;
    #pragma unroll
    for (int o = 16; o; o >>= 1) s += __shfl_xor_sync(0xffffffffu, s, o);
    float mu = s / (float)F;

    float var = 0.f;
    #pragma unroll
    for (int v = 0; v < V; v++) {
        if (!act[v]) continue;
        float dx = acc[v].x - mu, dy = acc[v].y - mu, dz = acc[v].z - mu, dw = acc[v].w - mu;
        var += dx * dx + dy * dy + dz * dz + dw * dw;
    }
    #pragma unroll
    for (int o = 16; o; o >>= 1) var += __shfl_xor_sync(0xffffffffu, var, o);
    float rstd = rsqrtf(var / (float)F + 1e-5f);

    #pragma unroll
    for (int v = 0; v < V; v++) {
        if (!act[v]) continue;
        int idx = lane + v * 32;
        float4 gv = reinterpret_cast<const float4*>(g)[idx];
        float4 bv = reinterpret_cast<const float4*>(be)[idx];
        float4 r;
        r.x = (acc[v].x - mu) * rstd * gv.x + bv.x;
        r.y = (acc[v].y - mu) * rstd * gv.y + bv.y;
        r.z = (acc[v].z - mu) * rstd * gv.z + bv.z;
        r.w = (acc[v].w - mu) * rstd * gv.w + bv.w;
        r.x = (r.x > 0.f) ? r.x : expm1f(r.x);
        r.y = (r.y > 0.f) ? r.y : expm1f(r.y);
        r.z = (r.z > 0.f) ? r.z : expm1f(r.z);
        r.w = (r.w > 0.f) ? r.w : expm1f(r.w);
        x4[(size_t)node * RS + idx] = r;
    }
}

// ---------------- tf32 tensor-core GEMM, BM=128 BN=128 BK=16, double-buffered ----------------
#define GBM 128
#define GBN 128
#define GBK 16
#define AS_STRIDE 136
#define BS_STRIDE 136

__device__ __forceinline__ uint32_t f2tf32(float f) {
    uint32_t r;
    asm("cvt.rna.tf32.f32 %0, %1;" : "=r"(r) : "f"(f));
    return r;
}

template <bool BIAS>
__global__ void __launch_bounds__(256) gemm_tf32_kernel(
    const float* __restrict__ A, const float* __restrict__ W,
    const float* __restrict__ bias, float* __restrict__ C,
    int M, int K, int Nc) {
    __shared__ uint32_t As[2][GBK][AS_STRIDE];
    __shared__ uint32_t Bs[2][GBK][BS_STRIDE];

    int tid = threadIdx.x;
    int warp = tid >> 5, lane = tid & 31;
    int warpM = warp & 3;        // 4 warps along M (32 rows each)
    int warpN = warp >> 2;       // 2 warps along N (64 cols each)
    int blockM = blockIdx.y * GBM;
    int blockN = blockIdx.x * GBN;

    float c[2][8][4];
    #pragma unroll
    for (int mi = 0; mi < 2; mi++)
        #pragma unroll
        for (int ni = 0; ni < 8; ni++)
            #pragma unroll
            for (int r = 0; r < 4; r++) c[mi][ni][r] = 0.f;

    // A staging: each thread loads 8 floats of one row
    int arow = tid >> 1;
    int acg  = (tid & 1) << 3;
    int aRowG = blockM + arow;
    bool aValid = aRowG < M;
    const float* Aptr = A + (size_t)aRowG * K + acg;
    // B staging: each thread loads 8 floats (two float4) of one row
    int brow = tid >> 4;                 // 0..15
    int bcol = (tid & 15) << 3;          // 0..120
    bool bValid0 = (blockN + bcol) < Nc;
    bool bValid1 = (blockN + bcol + 4) < Nc;

    int mrow = lane >> 2;
    int kcol = lane & 3;

    // prologue
    {
        float4 v0 = make_float4(0.f, 0.f, 0.f, 0.f);
        float4 v1 = make_float4(0.f, 0.f, 0.f, 0.f);
        if (aValid) {
            v0 = *reinterpret_cast<const float4*>(Aptr);
            v1 = *reinterpret_cast<const float4*>(Aptr + 4);
        }
        As[0][acg + 0][arow] = f2tf32(v0.x);
        As[0][acg + 1][arow] = f2tf32(v0.y);
        As[0][acg + 2][arow] = f2tf32(v0.z);
        As[0][acg + 3][arow] = f2tf32(v0.w);
        As[0][acg + 4][arow] = f2tf32(v1.x);
        As[0][acg + 5][arow] = f2tf32(v1.y);
        As[0][acg + 6][arow] = f2tf32(v1.z);
        As[0][acg + 7][arow] = f2tf32(v1.w);
        float4 w0 = make_float4(0.f, 0.f, 0.f, 0.f);
        float4 w1 = make_float4(0.f, 0.f, 0.f, 0.f);
        if (bValid0) w0 = *reinterpret_cast<const float4*>(W + (size_t)brow * Nc + blockN + bcol);
        if (bValid1) w1 = *reinterpret_cast<const float4*>(W + (size_t)brow * Nc + blockN + bcol + 4);
        Bs[0][brow][bcol + 0] = f2tf32(w0.x);
        Bs[0][brow][bcol + 1] = f2tf32(w0.y);
        Bs[0][brow][bcol + 2] = f2tf32(w0.z);
        Bs[0][brow][bcol + 3] = f2tf32(w0.w);
        Bs[0][brow][bcol + 4] = f2tf32(w1.x);
        Bs[0][brow][bcol + 5] = f2tf32(w1.y);
        Bs[0][brow][bcol + 6] = f2tf32(w1.z);
        Bs[0][brow][bcol + 7] = f2tf32(w1.w);
    }
    __syncthreads();

    int buf = 0;
    for (int k0 = 0; k0 < K; k0 += GBK) {
        bool nxt = (k0 + GBK) < K;
        float4 v0n, v1n, w0n, w1n;
        if (nxt) {
            v0n = make_float4(0.f, 0.f, 0.f, 0.f);
            v1n = make_float4(0.f, 0.f, 0.f, 0.f);
            if (aValid) {
                v0n = *reinterpret_cast<const float4*>(Aptr + k0 + GBK);
                v1n = *reinterpret_cast<const float4*>(Aptr + k0 + GBK + 4);
            }
            w0n = make_float4(0.f, 0.f, 0.f, 0.f);
            w1n = make_float4(0.f, 0.f, 0.f, 0.f);
            const float* Wp = W + (size_t)(k0 + GBK + brow) * Nc + blockN + bcol;
            if (bValid0) w0n = *reinterpret_cast<const float4*>(Wp);
            if (bValid1) w1n = *reinterpret_cast<const float4*>(Wp + 4);
        }

        #pragma unroll
        for (int kk = 0; kk < GBK; kk += 8) {
            uint32_t a[2][4];
            #pragma unroll
            for (int mi = 0; mi < 2; mi++) {
                int r = warpM * 32 + mi * 16 + mrow;
                a[mi][0] = As[buf][kk + kcol][r];
                a[mi][1] = As[buf][kk + kcol][r + 8];
                a[mi][2] = As[buf][kk + kcol + 4][r];
                a[mi][3] = As[buf][kk + kcol + 4][r + 8];
            }
            uint32_t b[8][2];
            #pragma unroll
            for (int ni = 0; ni < 8; ni++) {
                int n = warpN * 64 + ni * 8 + mrow;
                b[ni][0] = Bs[buf][kk + kcol][n];
                b[ni][1] = Bs[buf][kk + kcol + 4][n];
            }
            #pragma unroll
            for (int mi = 0; mi < 2; mi++)
                #pragma unroll
                for (int ni = 0; ni < 8; ni++) {
                    asm volatile(
                        "mma.sync.aligned.m16n8k8.row.col.f32.tf32.tf32.f32 "
                        "{%0,%1,%2,%3}, {%4,%5,%6,%7}, {%8,%9}, {%0,%1,%2,%3};\n"
                        : "+f"(c[mi][ni][0]), "+f"(c[mi][ni][1]),
                          "+f"(c[mi][ni][2]), "+f"(c[mi][ni][3])
                        : "r"(a[mi][0]), "r"(a[mi][1]), "r"(a[mi][2]), "r"(a[mi][3]),
                          "r"(b[ni][0]), "r"(b[ni][1]));
                }
        }

        if (nxt) {
            int nb = buf ^ 1;
            As[nb][acg + 0][arow] = f2tf32(v0n.x);
            As[nb][acg + 1][arow] = f2tf32(v0n.y);
            As[nb][acg + 2][arow] = f2tf32(v0n.z);
            As[nb][acg + 3][arow] = f2tf32(v0n.w);
            As[nb][acg + 4][arow] = f2tf32(v1n.x);
            As[nb][acg + 5][arow] = f2tf32(v1n.y);
            As[nb][acg + 6][arow] = f2tf32(v1n.z);
            As[nb][acg + 7][arow] = f2tf32(v1n.w);
            Bs[nb][brow][bcol + 0] = f2tf32(w0n.x);
            Bs[nb][brow][bcol + 1] = f2tf32(w0n.y);
            Bs[nb][brow][bcol + 2] = f2tf32(w0n.z);
            Bs[nb][brow][bcol + 3] = f2tf32(w0n.w);
            Bs[nb][brow][bcol + 4] = f2tf32(w1n.x);
            Bs[nb][brow][bcol + 5] = f2tf32(w1n.y);
            Bs[nb][brow][bcol + 6] = f2tf32(w1n.z);
            Bs[nb][brow][bcol + 7] = f2tf32(w1n.w);
            __syncthreads();
            buf = nb;
        }
    }

    #pragma unroll
    for (int mi = 0; mi < 2; mi++) {
        int r0 = blockM + warpM * 32 + mi * 16 + mrow;
        #pragma unroll
        for (int ni = 0; ni < 8; ni++) {
            int cc = blockN + warpN * 64 + ni * 8 + kcol * 2;
            float bv0 = 0.f, bv1 = 0.f;
            if (BIAS) {
                if (cc < Nc) bv0 = bias[cc];
                if (cc + 1 < Nc) bv1 = bias[cc + 1];
            }
            if (r0 < M) {
                if (cc < Nc)     C[(size_t)r0 * Nc + cc]     = c[mi][ni][0] + bv0;
                if (cc + 1 < Nc) C[(size_t)r0 * Nc + cc + 1] = c[mi][ni][1] + bv1;
            }
            if (r0 + 8 < M) {
                if (cc < Nc)     C[(size_t)(r0 + 8) * Nc + cc]     = c[mi][ni][2] + bv0;
                if (cc + 1 < Nc) C[(size_t)(r0 + 8) * Nc + cc + 1] = c[mi][ni][3] + bv1;
            }
        }
    }
}

static inline void launch_gemm(const float* A, const float* W, const float* bias, float* C,
                               int M, int K, int Nc) {
    dim3 grid((Nc + GBN - 1) / GBN, (M + GBM - 1) / GBM);
    if (bias)
        gemm_tf32_kernel<true><<<grid, 256>>>(A, W, bias, C, M, K, Nc);
    else
        gemm_tf32_kernel<false><<<grid, 256>>>(A, W, nullptr, C, M, K, Nc);
}

extern "C" void kernel_launch(void* const* d_in, const int* in_sizes, int n_in,
                              void* d_out, int out_size) {
    const float* x   = (const float*)d_in[0];
    const int*   ei  = (const int*)d_in[1];
    const float* W1  = (const float*)d_in[2];
    const float* b1  = (const float*)d_in[3];
    const float* g1  = (const float*)d_in[4];
    const float* be1 = (const float*)d_in[5];
    const float* W2  = (const float*)d_in[6];
    const float* b2  = (const float*)d_in[7];
    const float* g2  = (const float*)d_in[8];
    const float* be2 = (const float*)d_in[9];
    const float* W3  = (const float*)d_in[10];
    const float* b3  = (const float*)d_in[11];
    const float* g3  = (const float*)d_in[12];
    const float* be3 = (const float*)d_in[13];
    const float* Wl1 = (const float*)d_in[14];
    const float* bl1 = (const float*)d_in[15];
    const float* g4  = (const float*)d_in[16];
    const float* be4 = (const float*)d_in[17];
    const float* Wl2 = (const float*)d_in[18];
    const float* bl2 = (const float*)d_in[19];
    float* out = (float*)d_out;

    const int N = in_sizes[0] / 128;
    const int E = in_sizes[1] / 2;
    const int* src = ei;
    const int* dst = ei + E;

    float *dinv, *bufA, *bufB, *csr_coef;
    int *cnt, *rowptr, *cursor, *csr_src, *partial;
    cudaGetSymbolAddress((void**)&dinv,     d_dinv);
    cudaGetSymbolAddress((void**)&cnt,      d_cnt);
    cudaGetSymbolAddress((void**)&rowptr,   d_rowptr);
    cudaGetSymbolAddress((void**)&cursor,   d_cursor);
    cudaGetSymbolAddress((void**)&partial,  d_partial);
    cudaGetSymbolAddress((void**)&csr_src,  d_csr_src);
    cudaGetSymbolAddress((void**)&csr_coef, d_csr_coef);
    cudaGetSymbolAddress((void**)&bufA,     d_bufA);
    cudaGetSymbolAddress((void**)&bufB,     d_bufB);

    // ---- CSR build ----
    int nBlocks = (N + SCAN_BLK - 1) / SCAN_BLK;
    cudaMemsetAsync(cnt, 0, (size_t)N * sizeof(int));
    count_kernel<<<(E + 255) / 256, 256>>>(dst, cnt, E);
    block_reduce_kernel<<<nBlocks, SCAN_BLK>>>(cnt, partial, N);
    scan_partials_kernel<<<1, SCAN_BLK>>>(partial, nBlocks);
    scan_final_kernel<<<nBlocks, SCAN_BLK>>>(cnt, partial, rowptr, cursor, dinv, N);
    fill_kernel<<<(E + 255) / 256, 256>>>(src, dst, dinv, cursor, csr_src, csr_coef, E);

    int gatherGrid = (N + 7) / 8;

    // ---- layer 1 (128->128): gemm -> gather+LN+ELU
    launch_gemm(x, W1, nullptr, bufA, N, 128, 128);
    gather_warp_kernel<128, true><<<gatherGrid, 256>>>(bufA, rowptr, csr_src, csr_coef,
                                                       dinv, b1, g1, be1, bufB, N);

    // ---- layer 2 (128->256): aggregate first, then gemm(+bias), then LN
    gather_warp_kernel<128, false><<<gatherGrid, 256>>>(bufB, rowptr, csr_src, csr_coef,
                                                        dinv, nullptr, nullptr, nullptr, bufA, N);
    launch_gemm(bufA, W2, b2, bufB, N, 128, 256);
    ln_elu_warp_kernel<256><<<gatherGrid, 256>>>(bufB, g2, be2, N);

    // ---- layer 3 (256->128): gemm -> gather+LN+ELU
    launch_gemm(bufB, W3, nullptr, bufA, N, 256, 128);
    gather_warp_kernel<128, true><<<gatherGrid, 256>>>(bufA, rowptr, csr_src, csr_coef,
                                                       dinv, b3, g3, be3, bufB, N);

    // ---- head: linear -> LN -> ELU -> linear
    launch_gemm(bufB, Wl1, bl1, bufA, N, 128, 64);
    ln_elu_warp_kernel<64><<<gatherGrid, 256>>>(bufA, g4, be4, N);
    launch_gemm(bufA, Wl2, bl2, out, N, 64, 500);
}